// round 14
// baseline (speedup 1.0000x reference)
#include <cuda_runtime.h>
#include <cuda_fp16.h>
#include <cstdint>

// ---- lc_kernel smem layout (32-bit words) ----
#define U_BUF_W   8192          // one u buffer: 16l*16k*128B = 32KB
#define WSM_OFF   24576         // after 3 u buffers
#define WQS 552                 // w q-stride (16*34 + 8)
#define WLS 34                  // w l-stride (32 o + 2 pad)
#define WBUFW 4416              // 8 * 552
#define KOFF_OFF  33408         // after 2 w buffers
#define SEP_BS 34
#define SEP_PS 2176             // 64 * 34
#define SMEM_BYTES (34816 * 4)  // epilogue staging is the max user

__device__ __align__(256) __half g_xh[64 * 34 * 34 * 64];  // [c][hp][wp][b] fp16

__device__ __forceinline__ uint32_t f16x2(float hi, float lo) {
    uint32_t d; asm("cvt.rn.f16x2.f32 %0,%1,%2;" : "=r"(d) : "f"(hi), "f"(lo)); return d;
}
__device__ __forceinline__ uint32_t s2u(const void* p) {
    uint32_t a;
    asm("{.reg .u64 t; cvta.to.shared.u64 t,%1; cvt.u32.u64 %0,t;}" : "=r"(a) : "l"(p));
    return a;
}
#define MMAF16(d, a, b) asm volatile( \
    "mma.sync.aligned.m16n8k16.row.col.f32.f16.f16.f32 " \
    "{%0,%1,%2,%3},{%4,%5,%6,%7},{%8,%9},{%0,%1,%2,%3};" \
    : "+f"((d)[0]), "+f"((d)[1]), "+f"((d)[2]), "+f"((d)[3]) \
    : "r"((a)[0]), "r"((a)[1]), "r"((a)[2]), "r"((a)[3]), "r"((b)[0]), "r"((b)[1]))

// ---------------------------------------------------------------------------
// prep_kernel: blocks [0,2048) transpose x -> g_xh; blocks [2048, 2312) zero
// the padded border.
// ---------------------------------------------------------------------------
__global__ void prep_kernel(const float* __restrict__ x) {
    int tid = threadIdx.x;
    if (blockIdx.x >= 2048) {
        int idx = (blockIdx.x - 2048) * 256 + tid;     // 64c * 132 cells * 8
        if (idx >= 64 * 132 * 8) return;
        int g8 = idx & 7, r = idx >> 3;
        int c = r / 132, cell = r % 132;
        int hp, wp;
        if (cell < 34)       { hp = 0;  wp = cell; }
        else if (cell < 68)  { hp = 33; wp = cell - 34; }
        else if (cell < 100) { hp = cell - 68 + 1;  wp = 0; }
        else                 { hp = cell - 100 + 1; wp = 33; }
        *(uint4*)&g_xh[((c * 34 + hp) * 34 + wp) * 64 + g8 * 8] = make_uint4(0, 0, 0, 0);
        return;
    }
    __shared__ float t[32][65];
    int c = blockIdx.x & 63, h = blockIdx.x >> 6;
    int w = tid & 31, b0 = tid >> 5;
#pragma unroll
    for (int p = 0; p < 8; p++)
        t[w][b0 * 8 + p] = x[(((b0 * 8 + p) * 64 + c) * 32 + h) * 32 + w];
    __syncthreads();
    int b = tid & 63, wq = tid >> 6;
#pragma unroll
    for (int p = 0; p < 8; p++) {
        int ww = wq * 8 + p;
        g_xh[((c * 34 + h + 1) * 34 + ww + 1) * 64 + b] = __float2half_rn(t[ww][b]);
    }
}

// ---------------------------------------------------------------------------
// lc_kernel: 128 CTAs = 64 l-tiles x 2 o-halves. CTA = 16 l x 32 o x 64 b.
// 512 threads = 16 warps; warp <-> pixel (M64(b) x N32(o) per pixel).
// u: cp.async (3-deep) -> swizzled [l][k][b] fp16 tile -> ldmatrix.x4.trans.
// w: LDG f32 -> cvt f16x2 -> STS (double-buffered).
// ---------------------------------------------------------------------------
__global__ __launch_bounds__(512, 1)
void lc_kernel(const float* __restrict__ weight, const float* __restrict__ bias,
               float* __restrict__ out) {
    extern __shared__ uint32_t sm[];
    uint32_t* wsm = sm + WSM_OFF;
    int* koff = (int*)(sm + KOFF_OFF);
    const uint32_t sbase = s2u(sm);

    const int tid = threadIdx.x, lane = tid & 31, wrp = tid >> 5;
    const int l_tile = blockIdx.x >> 1, o0 = (blockIdx.x & 1) << 5;
    const int l0 = l_tile << 4;
    const int h = l0 >> 5, w0 = l0 & 31;            // 16-aligned tile: single h
    const int cq = lane & 3, rr = lane >> 2;

    for (int k = tid; k < 576; k += 512) {
        int c = k / 9, r = k - 9 * c, i = r / 3, j = r - 3 * i;
        koff[k] = (c * 1156 + i * 34 + j) * 64;     // half-element units
    }

    // ---- u cp.async mapping: seg = tid&7, k = (tid>>3)&15, l = (tid>>7)+4i
    const int us8 = tid & 7, uk = (tid >> 3) & 15, ul = tid >> 7;
    const __half* usrc0 = g_xh + (h * 34 + w0 + ul) * 64 + us8 * 8;
    const uint32_t udst0 = sbase +
        (uint32_t)(ul * 2048 + uk * 128 + ((us8 ^ (uk & 7)) << 4));

    // ---- w fill: q0 = tid>>7, o = (tid>>2)&31, lq = tid&3 ----
    const int w_q0 = tid >> 7, w_o = (tid >> 2) & 31, w_lq = tid & 3;
    const float* wsrc = weight + (size_t)(o0 + w_o) * 576 * 1024 + l0 + w_lq * 4;

    // ---- ldmatrix lane mapping ----
    const int kr = (lane & 7) | ((lane & 16) >> 1);  // k-row 0..15
    const int bh = (lane >> 3) & 1;                  // b half (0: b0-7, 1: b8-15)
    const int k7 = kr & 7;
    const uint32_t lm_row = sbase + (uint32_t)(wrp * 2048 + kr * 128);

    float4 wv[4];
    auto issue_u = [&](int ch, int buf) {
        const __half* s = usrc0 + koff[ch * 16 + uk];
        uint32_t d = udst0 + (uint32_t)buf * 32768u;
#pragma unroll
        for (int i = 0; i < 4; i++)
            asm volatile("cp.async.cg.shared.global [%0],[%1],16;"
                         :: "r"(d + (uint32_t)i * 8192u), "l"(s + i * 256));
    };
    auto ldg_w = [&](int ch) {
        int kb = ch * 16 + 2 * w_q0;
        wv[0] = *(const float4*)(wsrc + (size_t)kb * 1024);
        wv[1] = *(const float4*)(wsrc + (size_t)(kb + 1) * 1024);
        wv[2] = *(const float4*)(wsrc + (size_t)(kb + 8) * 1024);
        wv[3] = *(const float4*)(wsrc + (size_t)(kb + 9) * 1024);
    };
    auto sts_w = [&](int buf) {
        uint32_t* dw = wsm + buf * WBUFW + (w_lq * 4) * WLS + w_o;
#pragma unroll
        for (int s = 0; s < 2; s++) {
            uint32_t* d = dw + (w_q0 + 4 * s) * WQS;
            float4 vk = wv[2 * s], vk1 = wv[2 * s + 1];
            d[0 * WLS] = f16x2(vk1.x, vk.x);
            d[1 * WLS] = f16x2(vk1.y, vk.y);
            d[2 * WLS] = f16x2(vk1.z, vk.z);
            d[3 * WLS] = f16x2(vk1.w, vk.w);
        }
    };

    float acc[16][4];
#pragma unroll
    for (int i = 0; i < 16; i++)
#pragma unroll
        for (int j = 0; j < 4; j++) acc[i][j] = 0.f;

    __syncthreads();                      // koff ready
    ldg_w(0);
    issue_u(0, 0); asm volatile("cp.async.commit_group;" ::: "memory");
    issue_u(1, 1); asm volatile("cp.async.commit_group;" ::: "memory");

    int ubm = 0;   // u buffer of chunk ch (mod 3)
    int ub2 = 2;   // u buffer of chunk ch+2 (mod 3)
    for (int ch = 0; ch < 36; ch++) {
        const int p = ch & 1;
        sts_w(p);
        if (ch + 2 < 36) issue_u(ch + 2, ub2);
        asm volatile("cp.async.commit_group;" ::: "memory");
        if (ch < 35) ldg_w(ch + 1);
        asm volatile("cp.async.wait_group 2;" ::: "memory");
        __syncthreads();

        // B fragments (w)
        const uint32_t* B = wsm + p * WBUFW + cq * WQS + wrp * WLS + rr;
        uint32_t bfr[4][2];
#pragma unroll
        for (int nt = 0; nt < 4; nt++) {
            bfr[nt][0] = B[nt * 8];
            bfr[nt][1] = B[4 * WQS + nt * 8];
        }
        // A fragments (u) via ldmatrix.trans + MMAs
        const uint32_t abase = lm_row + (uint32_t)ubm * 32768u;
#pragma unroll
        for (int mt = 0; mt < 4; mt++) {
            uint32_t a[4];
            uint32_t ad = abase + (uint32_t)((((2 * mt + bh) ^ k7) << 4));
            asm volatile("ldmatrix.sync.aligned.m8n8.x4.trans.shared.b16 "
                         "{%0,%1,%2,%3},[%4];"
                         : "=r"(a[0]), "=r"(a[1]), "=r"(a[2]), "=r"(a[3]) : "r"(ad));
#pragma unroll
            for (int nt = 0; nt < 4; nt++)
                MMAF16(acc[mt * 4 + nt], a, bfr[nt]);
        }
        ubm = (ubm == 2) ? 0 : ubm + 1;
        ub2 = (ub2 == 2) ? 0 : ub2 + 1;
        // single sync per chunk: w buf p rewritten at ch+2 (after sync ch+1);
        // u bufs are mod-3 so the cp.async issued above never targets a live buf.
    }
    __syncthreads();

    // ---- epilogue: sep[pix][b][o] staging, then 64B coalesced rows ----
    float* sep = (float*)sm;
#pragma unroll
    for (int mt = 0; mt < 4; mt++)
#pragma unroll
        for (int nt = 0; nt < 4; nt++) {
            const float* d = acc[mt * 4 + nt];
            int b = mt * 16 + rr, o = nt * 8 + 2 * cq;
            float* pp = sep + wrp * SEP_PS + b * SEP_BS + o;
            *(float2*)pp                = make_float2(d[0], d[1]);
            *(float2*)(pp + 8 * SEP_BS) = make_float2(d[2], d[3]);
        }
    __syncthreads();
#pragma unroll
    for (int it = 0; it < 4; it++) {
        int unit = tid + (it << 9);
        int o = unit & 31, b = unit >> 5;
        float v[16];
#pragma unroll
        for (int l = 0; l < 16; l++) v[l] = sep[l * SEP_PS + b * SEP_BS + o];
        const float* bp = bias + (size_t)(o0 + o) * 1024 + l0;
        float* dp = out + ((size_t)(b * 64 + o0 + o)) * 1024 + l0;
#pragma unroll
        for (int g = 0; g < 4; g++) {
            float4 bv = *(const float4*)(bp + 4 * g);
            *(float4*)(dp + 4 * g) = make_float4(v[4 * g] + bv.x, v[4 * g + 1] + bv.y,
                                                 v[4 * g + 2] + bv.z, v[4 * g + 3] + bv.w);
        }
    }
}

// ---------------------------------------------------------------------------
extern "C" void kernel_launch(void* const* d_in, const int* in_sizes, int n_in,
                              void* d_out, int out_size) {
    const float* x      = (const float*)d_in[0];
    const float* weight = (const float*)d_in[1];
    const float* bias   = (const float*)d_in[2];
    float* out = (float*)d_out;

    cudaFuncSetAttribute(lc_kernel, cudaFuncAttributeMaxDynamicSharedMemorySize, SMEM_BYTES);

    prep_kernel<<<2048 + 264, 256>>>(x);
    lc_kernel<<<128, 512, SMEM_BYTES>>>(weight, bias, out);
}